// round 12
// baseline (speedup 1.0000x reference)
#include <cuda_runtime.h>
#include <cuda_fp16.h>
#include <cuda_bf16.h>
#include <cstdint>

#define N_NODES 50000
#define N_EDGES 1600000
#define IN_F 256
#define OUT_F 64
#define TILE_M 128
#define K_CHUNK 64
#define SLOT_CAP 128

#define GEMM_BLOCKS ((N_NODES + TILE_M - 1) / TILE_M)          // 391
#define EPT 8
#define FILL_BLOCKS ((N_EDGES + 256 * EPT - 1) / (256 * EPT))  // 782
// total = 1173 = 3 * 391; role = bid % 3 (0 -> gemm, 1/2 -> fill)

__device__ __half g_h[N_NODES * OUT_F];        // relu(xW^T+b) fp16, 6.4MB
__device__ int    g_cnt[N_NODES];              // zero-init; gather resets it
__device__ int    g_slots[N_NODES * SLOT_CAP]; // src lists per dst, 25.6MB

// ---------------- PTX helpers -----------------------------------------------
__device__ __forceinline__ uint32_t smem_u32(const void* p) {
    uint32_t a;
    asm("{ .reg .u64 t; cvta.to.shared.u64 t, %1; cvt.u32.u64 %0, t; }"
        : "=r"(a) : "l"(p));
    return a;
}
__device__ __forceinline__ void ldsm4(uint32_t* r, uint32_t addr) {
    asm volatile("ldmatrix.sync.aligned.m8n8.x4.shared.b16 {%0,%1,%2,%3}, [%4];"
                 : "=r"(r[0]), "=r"(r[1]), "=r"(r[2]), "=r"(r[3]) : "r"(addr));
}
__device__ __forceinline__ void mma16816(float* c, const uint32_t* a,
                                         const uint32_t* b) {
    asm volatile(
        "mma.sync.aligned.m16n8k16.row.col.f32.bf16.bf16.f32 "
        "{%0,%1,%2,%3}, {%4,%5,%6,%7}, {%8,%9}, {%0,%1,%2,%3};"
        : "+f"(c[0]), "+f"(c[1]), "+f"(c[2]), "+f"(c[3])
        : "r"(a[0]), "r"(a[1]), "r"(a[2]), "r"(a[3]), "r"(b[0]), "r"(b[1]));
}

// bf16 hi/lo split of 8 floats (two float4) -> 16B hi + 16B lo
__device__ __forceinline__ void split8(float4 v0, float4 v1,
                                       uint4& hi, uint4& lo) {
    __nv_bfloat162 h;
    uint32_t uh[4];
    float4 vv[2] = { v0, v1 };
    float  rl[8];
    #pragma unroll
    for (int i = 0; i < 2; i++) {
        h = __floats2bfloat162_rn(vv[i].x, vv[i].y);
        uh[2 * i] = *(uint32_t*)&h;
        rl[4 * i + 0] = vv[i].x - __uint_as_float(uh[2 * i] << 16);
        rl[4 * i + 1] = vv[i].y - __uint_as_float(uh[2 * i] & 0xFFFF0000u);
        h = __floats2bfloat162_rn(vv[i].z, vv[i].w);
        uh[2 * i + 1] = *(uint32_t*)&h;
        rl[4 * i + 2] = vv[i].z - __uint_as_float(uh[2 * i + 1] << 16);
        rl[4 * i + 3] = vv[i].w - __uint_as_float(uh[2 * i + 1] & 0xFFFF0000u);
    }
    hi = make_uint4(uh[0], uh[1], uh[2], uh[3]);
    uint32_t ul[4];
    #pragma unroll
    for (int i = 0; i < 4; i++) {
        h = __floats2bfloat162_rn(rl[2 * i], rl[2 * i + 1]);
        ul[i] = *(uint32_t*)&h;
    }
    lo = make_uint4(ul[0], ul[1], ul[2], ul[3]);
}

// ---------------- mega: interleaved HMMA-GEMM + bucket-fill blocks -----------
__global__ void __launch_bounds__(256, 2) mega_kernel(
        const float* __restrict__ x, const float* __restrict__ W,
        const float* __restrict__ bias,
        const int* __restrict__ esrc, const int* __restrict__ edst) {

    const int bid = blockIdx.x;

    // ---- fill path (bid % 3 != 0) ----
    if (bid % 3 != 0) {
        int fb = bid - bid / 3 - 1;               // 0 .. FILL_BLOCKS-1
        long t = (long)fb * 256 + threadIdx.x;
        long base = t * EPT;
        if (base + EPT <= N_EDGES) {
            int4 s0 = *(const int4*)(esrc + base);
            int4 s1 = *(const int4*)(esrc + base + 4);
            int4 d0 = *(const int4*)(edst + base);
            int4 d1 = *(const int4*)(edst + base + 4);
            int p;
            p = atomicAdd(&g_cnt[d0.x], 1); if (p < SLOT_CAP) g_slots[d0.x * SLOT_CAP + p] = s0.x;
            p = atomicAdd(&g_cnt[d0.y], 1); if (p < SLOT_CAP) g_slots[d0.y * SLOT_CAP + p] = s0.y;
            p = atomicAdd(&g_cnt[d0.z], 1); if (p < SLOT_CAP) g_slots[d0.z * SLOT_CAP + p] = s0.z;
            p = atomicAdd(&g_cnt[d0.w], 1); if (p < SLOT_CAP) g_slots[d0.w * SLOT_CAP + p] = s0.w;
            p = atomicAdd(&g_cnt[d1.x], 1); if (p < SLOT_CAP) g_slots[d1.x * SLOT_CAP + p] = s1.x;
            p = atomicAdd(&g_cnt[d1.y], 1); if (p < SLOT_CAP) g_slots[d1.y * SLOT_CAP + p] = s1.y;
            p = atomicAdd(&g_cnt[d1.z], 1); if (p < SLOT_CAP) g_slots[d1.z * SLOT_CAP + p] = s1.z;
            p = atomicAdd(&g_cnt[d1.w], 1); if (p < SLOT_CAP) g_slots[d1.w * SLOT_CAP + p] = s1.w;
        } else {
            for (long e = base; e < N_EDGES; ++e) {
                int s = esrc[e], d = edst[e];
                int p = atomicAdd(&g_cnt[d], 1);
                if (p < SLOT_CAP) g_slots[d * SLOT_CAP + p] = s;
            }
        }
        return;
    }

    // ---- gemm path (bid % 3 == 0): h = relu(x W^T + b), bf16 hi/lo HMMA ----
    __shared__ __align__(128) uint8_t smAh[16384];
    __shared__ __align__(128) uint8_t smAl[16384];
    __shared__ __align__(128) uint8_t smBh[8192];
    __shared__ __align__(128) uint8_t smBl[8192];

    const int tid = threadIdx.x;
    const int wid = tid >> 5;
    const int lid = tid & 31;
    const int wm = wid >> 1;          // 0..3: rows [wm*32, wm*32+32)
    const int wn = wid & 1;           // 0..1: cols [wn*32, wn*32+32)
    const int node0 = (bid / 3) * TILE_M;

    const uint32_t sAh = smem_u32(smAh), sAl = smem_u32(smAl);
    const uint32_t sBh = smem_u32(smBh), sBl = smem_u32(smBl);

    float acc[2][4][4];
    #pragma unroll
    for (int i = 0; i < 2; i++)
        #pragma unroll
        for (int j = 0; j < 4; j++)
            #pragma unroll
            for (int k = 0; k < 4; k++) acc[i][j][k] = 0.f;

    const int q  = lid >> 3;          // ldmatrix matrix id
    const int ri = lid & 7;

    for (int c = 0; c < IN_F / K_CHUNK; ++c) {
        __syncthreads();
        #pragma unroll
        for (int it = 0; it < 4; ++it) {
            int idx = tid + it * 256;
            int row = idx >> 3, u = idx & 7;
            int gn = node0 + row;
            float4 v0 = make_float4(0.f, 0.f, 0.f, 0.f), v1 = v0;
            if (gn < N_NODES) {
                const float4* src = (const float4*)x + (size_t)gn * 64 + c * 16 + u * 2;
                v0 = src[0];
                v1 = src[1];
            }
            uint4 hi, lo;
            split8(v0, v1, hi, lo);
            uint32_t off = (uint32_t)(row * 128 + ((u ^ (row & 7)) << 4));
            *(uint4*)(smAh + off) = hi;
            *(uint4*)(smAl + off) = lo;
        }
        #pragma unroll
        for (int it = 0; it < 2; ++it) {
            int idx = tid + it * 256;
            int row = idx >> 3, u = idx & 7;
            const float4* src = (const float4*)W + (size_t)row * 64 + c * 16 + u * 2;
            float4 v0 = src[0];
            float4 v1 = src[1];
            uint4 hi, lo;
            split8(v0, v1, hi, lo);
            uint32_t off = (uint32_t)(row * 128 + ((u ^ (row & 7)) << 4));
            *(uint4*)(smBh + off) = hi;
            *(uint4*)(smBl + off) = lo;
        }
        __syncthreads();

        #pragma unroll
        for (int ks = 0; ks < K_CHUNK / 16; ++ks) {
            uint32_t ah[2][4], al[2][4];
            #pragma unroll
            for (int mt = 0; mt < 2; ++mt) {
                int row = wm * 32 + mt * 16 + (q & 1) * 8 + ri;
                int u = ks * 2 + (q >> 1);
                uint32_t off = (uint32_t)(row * 128 + ((u ^ (row & 7)) << 4));
                ldsm4(ah[mt], sAh + off);
                ldsm4(al[mt], sAl + off);
            }
            uint32_t bh[2][4], bl[2][4];
            #pragma unroll
            for (int p = 0; p < 2; ++p) {
                int n = wn * 32 + p * 16 + (q >> 1) * 8 + ri;
                int u = ks * 2 + (q & 1);
                uint32_t off = (uint32_t)(n * 128 + ((u ^ (n & 7)) << 4));
                ldsm4(bh[p], sBh + off);
                ldsm4(bl[p], sBl + off);
            }
            #pragma unroll
            for (int mt = 0; mt < 2; ++mt) {
                #pragma unroll
                for (int nt = 0; nt < 4; ++nt) {
                    const uint32_t* Bh = &bh[nt >> 1][(nt & 1) * 2];
                    const uint32_t* Bl = &bl[nt >> 1][(nt & 1) * 2];
                    mma16816(acc[mt][nt], ah[mt], Bh);   // hi*hi
                    mma16816(acc[mt][nt], ah[mt], Bl);   // hi*lo
                    mma16816(acc[mt][nt], al[mt], Bh);   // lo*hi
                }
            }
        }
    }

    // epilogue: +bias, relu, fp16 store to g_h
    const int lr = lid >> 2;
    const int lc = (lid & 3) * 2;
    #pragma unroll
    for (int mt = 0; mt < 2; ++mt) {
        int row0 = node0 + wm * 32 + mt * 16 + lr;
        #pragma unroll
        for (int nt = 0; nt < 4; ++nt) {
            int col = wn * 32 + nt * 8 + lc;
            float b0 = __ldg(bias + col);
            float b1 = __ldg(bias + col + 1);
            if (row0 < N_NODES) {
                float a0 = fmaxf(acc[mt][nt][0] + b0, 0.f);
                float a1 = fmaxf(acc[mt][nt][1] + b1, 0.f);
                __half2 h = __floats2half2_rn(a0, a1);
                *(uint32_t*)&g_h[(size_t)row0 * OUT_F + col] = *(uint32_t*)&h;
            }
            int row1 = row0 + 8;
            if (row1 < N_NODES) {
                float a2 = fmaxf(acc[mt][nt][2] + b0, 0.f);
                float a3 = fmaxf(acc[mt][nt][3] + b1, 0.f);
                __half2 h = __floats2half2_rn(a2, a3);
                *(uint32_t*)&g_h[(size_t)row1 * OUT_F + col] = *(uint32_t*)&h;
            }
        }
    }
}

// fp16 tree of 4 rows -> fp32 accumulate
__device__ __forceinline__ void addtree4(float* acc, const __half* hbase,
                                         int4 ss) {
    uint4 v0 = *(const uint4*)(hbase + (size_t)ss.x * OUT_F);
    uint4 v1 = *(const uint4*)(hbase + (size_t)ss.y * OUT_F);
    uint4 v2 = *(const uint4*)(hbase + (size_t)ss.z * OUT_F);
    uint4 v3 = *(const uint4*)(hbase + (size_t)ss.w * OUT_F);
    const __half2* p0 = (const __half2*)&v0;
    const __half2* p1 = (const __half2*)&v1;
    const __half2* p2 = (const __half2*)&v2;
    const __half2* p3 = (const __half2*)&v3;
    #pragma unroll
    for (int qq = 0; qq < 4; qq++) {
        __half2 s01 = __hadd2(p0[qq], p1[qq]);
        __half2 s23 = __hadd2(p2[qq], p3[qq]);
        __half2 s   = __hadd2(s01, s23);
        float2 f = __half22float2(s);
        acc[2 * qq]     += f.x;
        acc[2 * qq + 1] += f.y;
    }
}

// ---------------- gather + mean (+ counter reset for next replay) ------------
// 16 lanes per node in 2 halves of 8: half h processes int4 groups g = h, h+2,...
// Lane owns 8 feats; halves combined with shfl_xor(8). Halves the dependent
// slot->h chain per thread (gather is latency-bound: occ 58%, issue 37%).
__global__ void __launch_bounds__(256, 6) gather_kernel(float* __restrict__ out) {
    int t = blockIdx.x * blockDim.x + threadIdx.x;
    int n = t >> 4;
    if (n >= N_NODES) return;
    int half = (t >> 3) & 1;
    int lane = t & 7;

    int deg = g_cnt[n];
    int m = min(deg, SLOT_CAP);
    const int4* sl4 = (const int4*)&g_slots[n * SLOT_CAP];
    const __half* hbase = g_h + (size_t)lane * 8;

    float acc[8];
    #pragma unroll
    for (int j = 0; j < 8; j++) acc[j] = 0.f;

    int ngroups = m >> 2;
    for (int g = half; g < ngroups; g += 2) {
        int4 ss = __ldg(sl4 + g);
        addtree4(acc, hbase, ss);
    }
    // tail edges (m % 4): handled by half 1 (usually idle longer)
    if (half == 1) {
        const int* sl = (const int*)sl4;
        for (int j = ngroups << 2; j < m; ++j) {
            int s0 = __ldg(sl + j);
            uint4 v0 = *(const uint4*)(hbase + (size_t)s0 * OUT_F);
            const __half2* p0 = (const __half2*)&v0;
            #pragma unroll
            for (int qq = 0; qq < 4; qq++) {
                float2 f0 = __half22float2(p0[qq]);
                acc[2 * qq]     += f0.x;
                acc[2 * qq + 1] += f0.y;
            }
        }
    }

    // combine halves: warp lanes (t&31): 0..15 node A, 16..31 node B; xor 8
    // pairs lane l with l^8 — same node, other half.
    #pragma unroll
    for (int k = 0; k < 8; k++)
        acc[k] += __shfl_xor_sync(0xffffffffu, acc[k], 8);

    if (half == 0) {
        float inv = 1.0f / fmaxf((float)deg, 1.0f);
        float4 r0 = make_float4(acc[0] * inv, acc[1] * inv, acc[2] * inv, acc[3] * inv);
        float4 r1 = make_float4(acc[4] * inv, acc[5] * inv, acc[6] * inv, acc[7] * inv);
        float4* dst = (float4*)&out[(size_t)n * OUT_F + lane * 8];
        dst[0] = r0;
        dst[1] = r1;
        if (lane == 0) g_cnt[n] = 0;   // reset for next graph replay
    }
}

extern "C" void kernel_launch(void* const* d_in, const int* in_sizes, int n_in,
                              void* d_out, int out_size) {
    const float* x    = (const float*)d_in[0];
    const float* W    = (const float*)d_in[1];
    const float* b    = (const float*)d_in[2];
    const int*   esrc = (const int*)d_in[3];
    const int*   edst = (const int*)d_in[4];
    float*       out  = (float*)d_out;

    mega_kernel<<<GEMM_BLOCKS + FILL_BLOCKS, 256>>>(x, W, b, esrc, edst);
    gather_kernel<<<(N_NODES * 16 + 255) / 256, 256>>>(out);
}

// round 13
// speedup vs baseline: 1.0633x; 1.0633x over previous
#include <cuda_runtime.h>
#include <cuda_fp16.h>
#include <cuda_bf16.h>
#include <cstdint>

#define N_NODES 50000
#define N_EDGES 1600000
#define IN_F 256
#define OUT_F 64
#define TILE_M 128
#define K_CHUNK 64
#define SLOT_CAP 128

#define GEMM_BLOCKS ((N_NODES + TILE_M - 1) / TILE_M)          // 391
#define EPT 8
#define FILL_BLOCKS ((N_EDGES + 256 * EPT - 1) / (256 * EPT))  // 782
// total = 1173 = 3 * 391; role = bid % 3 (0 -> gemm, 1/2 -> fill)

__device__ __half g_h[N_NODES * OUT_F];        // relu(xW^T+b) fp16, 6.4MB
__device__ int    g_cnt[N_NODES];              // zero-init; gather resets it
__device__ int    g_slots[N_NODES * SLOT_CAP]; // src lists per dst, 25.6MB

// ---------------- PTX helpers -----------------------------------------------
__device__ __forceinline__ uint32_t smem_u32(const void* p) {
    uint32_t a;
    asm("{ .reg .u64 t; cvta.to.shared.u64 t, %1; cvt.u32.u64 %0, t; }"
        : "=r"(a) : "l"(p));
    return a;
}
__device__ __forceinline__ void ldsm4(uint32_t* r, uint32_t addr) {
    asm volatile("ldmatrix.sync.aligned.m8n8.x4.shared.b16 {%0,%1,%2,%3}, [%4];"
                 : "=r"(r[0]), "=r"(r[1]), "=r"(r[2]), "=r"(r[3]) : "r"(addr));
}
__device__ __forceinline__ void mma16816(float* c, const uint32_t* a,
                                         const uint32_t* b) {
    asm volatile(
        "mma.sync.aligned.m16n8k16.row.col.f32.bf16.bf16.f32 "
        "{%0,%1,%2,%3}, {%4,%5,%6,%7}, {%8,%9}, {%0,%1,%2,%3};"
        : "+f"(c[0]), "+f"(c[1]), "+f"(c[2]), "+f"(c[3])
        : "r"(a[0]), "r"(a[1]), "r"(a[2]), "r"(a[3]), "r"(b[0]), "r"(b[1]));
}

// bf16 hi/lo split of 8 floats (two float4) -> 16B hi + 16B lo
__device__ __forceinline__ void split8(float4 v0, float4 v1,
                                       uint4& hi, uint4& lo) {
    __nv_bfloat162 h;
    uint32_t uh[4];
    float4 vv[2] = { v0, v1 };
    float  rl[8];
    #pragma unroll
    for (int i = 0; i < 2; i++) {
        h = __floats2bfloat162_rn(vv[i].x, vv[i].y);
        uh[2 * i] = *(uint32_t*)&h;
        rl[4 * i + 0] = vv[i].x - __uint_as_float(uh[2 * i] << 16);
        rl[4 * i + 1] = vv[i].y - __uint_as_float(uh[2 * i] & 0xFFFF0000u);
        h = __floats2bfloat162_rn(vv[i].z, vv[i].w);
        uh[2 * i + 1] = *(uint32_t*)&h;
        rl[4 * i + 2] = vv[i].z - __uint_as_float(uh[2 * i + 1] << 16);
        rl[4 * i + 3] = vv[i].w - __uint_as_float(uh[2 * i + 1] & 0xFFFF0000u);
    }
    hi = make_uint4(uh[0], uh[1], uh[2], uh[3]);
    uint32_t ul[4];
    #pragma unroll
    for (int i = 0; i < 4; i++) {
        h = __floats2bfloat162_rn(rl[2 * i], rl[2 * i + 1]);
        ul[i] = *(uint32_t*)&h;
    }
    lo = make_uint4(ul[0], ul[1], ul[2], ul[3]);
}

// ---------------- mega: interleaved HMMA-GEMM + bucket-fill blocks -----------
__global__ void __launch_bounds__(256, 2) mega_kernel(
        const float* __restrict__ x, const float* __restrict__ W,
        const float* __restrict__ bias,
        const int* __restrict__ esrc, const int* __restrict__ edst) {

    const int bid = blockIdx.x;

    // ---- fill path (bid % 3 != 0) ----
    if (bid % 3 != 0) {
        int fb = bid - bid / 3 - 1;               // 0 .. FILL_BLOCKS-1
        long t = (long)fb * 256 + threadIdx.x;
        long base = t * EPT;
        if (base + EPT <= N_EDGES) {
            int4 s0 = *(const int4*)(esrc + base);
            int4 s1 = *(const int4*)(esrc + base + 4);
            int4 d0 = *(const int4*)(edst + base);
            int4 d1 = *(const int4*)(edst + base + 4);
            int p;
            p = atomicAdd(&g_cnt[d0.x], 1); if (p < SLOT_CAP) g_slots[d0.x * SLOT_CAP + p] = s0.x;
            p = atomicAdd(&g_cnt[d0.y], 1); if (p < SLOT_CAP) g_slots[d0.y * SLOT_CAP + p] = s0.y;
            p = atomicAdd(&g_cnt[d0.z], 1); if (p < SLOT_CAP) g_slots[d0.z * SLOT_CAP + p] = s0.z;
            p = atomicAdd(&g_cnt[d0.w], 1); if (p < SLOT_CAP) g_slots[d0.w * SLOT_CAP + p] = s0.w;
            p = atomicAdd(&g_cnt[d1.x], 1); if (p < SLOT_CAP) g_slots[d1.x * SLOT_CAP + p] = s1.x;
            p = atomicAdd(&g_cnt[d1.y], 1); if (p < SLOT_CAP) g_slots[d1.y * SLOT_CAP + p] = s1.y;
            p = atomicAdd(&g_cnt[d1.z], 1); if (p < SLOT_CAP) g_slots[d1.z * SLOT_CAP + p] = s1.z;
            p = atomicAdd(&g_cnt[d1.w], 1); if (p < SLOT_CAP) g_slots[d1.w * SLOT_CAP + p] = s1.w;
        } else {
            for (long e = base; e < N_EDGES; ++e) {
                int s = esrc[e], d = edst[e];
                int p = atomicAdd(&g_cnt[d], 1);
                if (p < SLOT_CAP) g_slots[d * SLOT_CAP + p] = s;
            }
        }
        return;
    }

    // ---- gemm path (bid % 3 == 0): h = relu(x W^T + b), bf16 hi/lo HMMA ----
    __shared__ __align__(128) uint8_t smAh[16384];
    __shared__ __align__(128) uint8_t smAl[16384];
    __shared__ __align__(128) uint8_t smBh[8192];
    __shared__ __align__(128) uint8_t smBl[8192];

    const int tid = threadIdx.x;
    const int wid = tid >> 5;
    const int lid = tid & 31;
    const int wm = wid >> 1;          // 0..3: rows [wm*32, wm*32+32)
    const int wn = wid & 1;           // 0..1: cols [wn*32, wn*32+32)
    const int node0 = (bid / 3) * TILE_M;

    const uint32_t sAh = smem_u32(smAh), sAl = smem_u32(smAl);
    const uint32_t sBh = smem_u32(smBh), sBl = smem_u32(smBl);

    float acc[2][4][4];
    #pragma unroll
    for (int i = 0; i < 2; i++)
        #pragma unroll
        for (int j = 0; j < 4; j++)
            #pragma unroll
            for (int k = 0; k < 4; k++) acc[i][j][k] = 0.f;

    const int q  = lid >> 3;          // ldmatrix matrix id
    const int ri = lid & 7;

    for (int c = 0; c < IN_F / K_CHUNK; ++c) {
        __syncthreads();
        #pragma unroll
        for (int it = 0; it < 4; ++it) {
            int idx = tid + it * 256;
            int row = idx >> 3, u = idx & 7;
            int gn = node0 + row;
            float4 v0 = make_float4(0.f, 0.f, 0.f, 0.f), v1 = v0;
            if (gn < N_NODES) {
                const float4* src = (const float4*)x + (size_t)gn * 64 + c * 16 + u * 2;
                v0 = src[0];
                v1 = src[1];
            }
            uint4 hi, lo;
            split8(v0, v1, hi, lo);
            uint32_t off = (uint32_t)(row * 128 + ((u ^ (row & 7)) << 4));
            *(uint4*)(smAh + off) = hi;
            *(uint4*)(smAl + off) = lo;
        }
        #pragma unroll
        for (int it = 0; it < 2; ++it) {
            int idx = tid + it * 256;
            int row = idx >> 3, u = idx & 7;
            const float4* src = (const float4*)W + (size_t)row * 64 + c * 16 + u * 2;
            float4 v0 = src[0];
            float4 v1 = src[1];
            uint4 hi, lo;
            split8(v0, v1, hi, lo);
            uint32_t off = (uint32_t)(row * 128 + ((u ^ (row & 7)) << 4));
            *(uint4*)(smBh + off) = hi;
            *(uint4*)(smBl + off) = lo;
        }
        __syncthreads();

        #pragma unroll
        for (int ks = 0; ks < K_CHUNK / 16; ++ks) {
            uint32_t ah[2][4], al[2][4];
            #pragma unroll
            for (int mt = 0; mt < 2; ++mt) {
                int row = wm * 32 + mt * 16 + (q & 1) * 8 + ri;
                int u = ks * 2 + (q >> 1);
                uint32_t off = (uint32_t)(row * 128 + ((u ^ (row & 7)) << 4));
                ldsm4(ah[mt], sAh + off);
                ldsm4(al[mt], sAl + off);
            }
            uint32_t bh[2][4], bl[2][4];
            #pragma unroll
            for (int p = 0; p < 2; ++p) {
                int n = wn * 32 + p * 16 + (q >> 1) * 8 + ri;
                int u = ks * 2 + (q & 1);
                uint32_t off = (uint32_t)(n * 128 + ((u ^ (n & 7)) << 4));
                ldsm4(bh[p], sBh + off);
                ldsm4(bl[p], sBl + off);
            }
            #pragma unroll
            for (int mt = 0; mt < 2; ++mt) {
                #pragma unroll
                for (int nt = 0; nt < 4; ++nt) {
                    const uint32_t* Bh = &bh[nt >> 1][(nt & 1) * 2];
                    const uint32_t* Bl = &bl[nt >> 1][(nt & 1) * 2];
                    mma16816(acc[mt][nt], ah[mt], Bh);   // hi*hi
                    mma16816(acc[mt][nt], ah[mt], Bl);   // hi*lo
                    mma16816(acc[mt][nt], al[mt], Bh);   // lo*hi
                }
            }
        }
    }

    // epilogue: +bias, relu, fp16 store to g_h
    const int lr = lid >> 2;
    const int lc = (lid & 3) * 2;
    #pragma unroll
    for (int mt = 0; mt < 2; ++mt) {
        int row0 = node0 + wm * 32 + mt * 16 + lr;
        #pragma unroll
        for (int nt = 0; nt < 4; ++nt) {
            int col = wn * 32 + nt * 8 + lc;
            float b0 = __ldg(bias + col);
            float b1 = __ldg(bias + col + 1);
            if (row0 < N_NODES) {
                float a0 = fmaxf(acc[mt][nt][0] + b0, 0.f);
                float a1 = fmaxf(acc[mt][nt][1] + b1, 0.f);
                __half2 h = __floats2half2_rn(a0, a1);
                *(uint32_t*)&g_h[(size_t)row0 * OUT_F + col] = *(uint32_t*)&h;
            }
            int row1 = row0 + 8;
            if (row1 < N_NODES) {
                float a2 = fmaxf(acc[mt][nt][2] + b0, 0.f);
                float a3 = fmaxf(acc[mt][nt][3] + b1, 0.f);
                __half2 h = __floats2half2_rn(a2, a3);
                *(uint32_t*)&g_h[(size_t)row1 * OUT_F + col] = *(uint32_t*)&h;
            }
        }
    }
}

// ---------------- gather + mean (+ counter reset for next replay) ------------
// 8 lanes per node, lane owns 8 feats. 4-edge fp16 tree reduce -> fp32 acc.
// (R9 configuration: measured 22.0us.)
__global__ void __launch_bounds__(256, 6) gather_kernel(float* __restrict__ out) {
    int t = blockIdx.x * blockDim.x + threadIdx.x;
    int n = t >> 3;
    if (n >= N_NODES) return;
    int lane = t & 7;

    int deg = g_cnt[n];
    int m = min(deg, SLOT_CAP);
    const int* sl = &g_slots[n * SLOT_CAP];
    const __half* hbase = g_h + (size_t)lane * 8;

    float acc[8];
    #pragma unroll
    for (int j = 0; j < 8; j++) acc[j] = 0.f;

    int j = 0;
    for (; j + 4 <= m; j += 4) {
        int4 ss = *(const int4*)(sl + j);       // broadcast across 8 lanes
        uint4 v0 = *(const uint4*)(hbase + (size_t)ss.x * OUT_F);
        uint4 v1 = *(const uint4*)(hbase + (size_t)ss.y * OUT_F);
        uint4 v2 = *(const uint4*)(hbase + (size_t)ss.z * OUT_F);
        uint4 v3 = *(const uint4*)(hbase + (size_t)ss.w * OUT_F);
        const __half2* p0 = (const __half2*)&v0;
        const __half2* p1 = (const __half2*)&v1;
        const __half2* p2 = (const __half2*)&v2;
        const __half2* p3 = (const __half2*)&v3;
        #pragma unroll
        for (int qq = 0; qq < 4; qq++) {
            __half2 s01 = __hadd2(p0[qq], p1[qq]);
            __half2 s23 = __hadd2(p2[qq], p3[qq]);
            __half2 s   = __hadd2(s01, s23);
            float2 f = __half22float2(s);
            acc[2 * qq]     += f.x;
            acc[2 * qq + 1] += f.y;
        }
    }
    for (; j < m; j++) {
        int s0 = __ldg(sl + j);
        uint4 v0 = *(const uint4*)(hbase + (size_t)s0 * OUT_F);
        const __half2* p0 = (const __half2*)&v0;
        #pragma unroll
        for (int qq = 0; qq < 4; qq++) {
            float2 f0 = __half22float2(p0[qq]);
            acc[2 * qq]     += f0.x;
            acc[2 * qq + 1] += f0.y;
        }
    }

    float inv = 1.0f / fmaxf((float)deg, 1.0f);
    float4 r0 = make_float4(acc[0] * inv, acc[1] * inv, acc[2] * inv, acc[3] * inv);
    float4 r1 = make_float4(acc[4] * inv, acc[5] * inv, acc[6] * inv, acc[7] * inv);
    float4* dst = (float4*)&out[(size_t)n * OUT_F + lane * 8];
    dst[0] = r0;
    dst[1] = r1;

    if (lane == 0) g_cnt[n] = 0;   // reset for next graph replay
}

extern "C" void kernel_launch(void* const* d_in, const int* in_sizes, int n_in,
                              void* d_out, int out_size) {
    const float* x    = (const float*)d_in[0];
    const float* W    = (const float*)d_in[1];
    const float* b    = (const float*)d_in[2];
    const int*   esrc = (const int*)d_in[3];
    const int*   edst = (const int*)d_in[4];
    float*       out  = (float*)d_out;

    mega_kernel<<<GEMM_BLOCKS + FILL_BLOCKS, 256>>>(x, W, b, esrc, edst);
    gather_kernel<<<(N_NODES * 8 + 255) / 256, 256>>>(out);
}